// round 16
// baseline (speedup 1.0000x reference)
#include <cuda_runtime.h>
#include <cstdint>

#define DI __device__ __forceinline__

// ---------------- problem constants ----------------
constexpr int NBN  = 512;                 // nodes
constexpr int TT   = 24;                  // T
constexpr int HIDC = 256;
constexpr int HORC = 24;
constexpr int NIDC = 64;
constexpr int DD   = TT + NBN * TT + NIDC; // 12376
constexpr int DP   = 12384;               // padded to /16 (= 774*16)
constexpr int MM   = 8 * NBN;             // 4096 rows
constexpr int SPLIT_MAX = 8;
constexpr int CAPR = 4096;                // sparse entries cap per row (smem)

// ---------------- scratch (__device__ globals; no allocs) ----------------
__device__ float g_x   [(size_t)MM * DP];               // ~203 MB
__device__ float g_bc  [(size_t)MM * DP];               // ~203 MB
__device__ float g_part[(size_t)SPLIT_MAX * MM * HIDC]; // 33.5 MB split-K partials
__device__ float g_hA[MM * HIDC];
__device__ float g_hB[MM * HIDC];
__device__ float g_F [MM * HORC];
__device__ float g_level[MM];
__device__ float g_winr[(size_t)3 * DP * HIDC];         // rounded+padded W_in

// ---------------- helpers ----------------
DI float tf32r(float x) {                 // round-to-nearest TF32 (fp32 container)
    unsigned o;
    asm("cvt.rna.tf32.f32 %0, %1;" : "=r"(o) : "f"(x));
    return __uint_as_float(o);
}

DI void mma8(float c[4], const unsigned a[4], const unsigned b[2]) {
    asm volatile(
        "mma.sync.aligned.m16n8k8.row.col.f32.tf32.tf32.f32 "
        "{%0,%1,%2,%3}, {%4,%5,%6,%7}, {%8,%9}, {%0,%1,%2,%3};\n"
        : "+f"(c[0]), "+f"(c[1]), "+f"(c[2]), "+f"(c[3])
        : "r"(a[0]), "r"(a[1]), "r"(a[2]), "r"(a[3]),
          "r"(b[0]), "r"(b[1]));
}

DI void ldsm4(unsigned r[4], uint32_t addr) {
    asm volatile("ldmatrix.sync.aligned.m8n8.x4.shared.b16 {%0,%1,%2,%3}, [%4];"
                 : "=r"(r[0]), "=r"(r[1]), "=r"(r[2]), "=r"(r[3]) : "r"(addr));
}

DI void cpa16(uint32_t saddr, const float* g) {
    asm volatile("cp.async.ca.shared.global [%0], [%1], 16;" :: "r"(saddr), "l"(g));
}
DI void cp_commit() { asm volatile("cp.async.commit_group;"); }
DI void cp_wait2()  { asm volatile("cp.async.wait_group 2;"); }

// ---------------- weight prep: W_in rounded + padded (blocks 1,2 GEMM-A) ----------------
__global__ void prep_win_kernel(const float* __restrict__ Win) {
    constexpr int W4 = 3 * DP * HIDC / 4;
    int idx = blockIdx.x * 256 + threadIdx.x;
    if (idx >= W4) return;
    int n4   = idx % (HIDC / 4);
    int rest = idx / (HIDC / 4);                 // k + DP*blk
    int k    = rest % DP;
    int blk  = rest / DP;
    float4 v = make_float4(0.f, 0.f, 0.f, 0.f);
    if (k < DD) {
        v = *reinterpret_cast<const float4*>(Win + ((size_t)blk * DD + k) * HIDC + n4 * 4);
        v.x = tf32r(v.x); v.y = tf32r(v.y); v.z = tf32r(v.z); v.w = tf32r(v.w);
    }
    reinterpret_cast<float4*>(g_winr)[idx] = v;
}

// ---------------- fused: build x + sparse compaction + block-0 input layer ----------------
__global__ __launch_bounds__(256) void bx_fc0_kernel(
        const float* __restrict__ hist, const int* __restrict__ nid,
        const float* __restrict__ adj,  const float* __restrict__ emb,
        const float* __restrict__ W,    const float* __restrict__ bias,
        float* __restrict__ out) {
    int r = blockIdx.x;
    const int tid = threadIdx.x;
    const float* adjr  = adj  + (size_t)r * NBN;
    const float* histb = hist + (size_t)(r >> 9) * NBN * TT;
    const float* histr = hist + (size_t)r * TT;
    float* xr = g_x + (size_t)r * DP;

    __shared__ float s_inv;
    __shared__ int   s_c[256];
    __shared__ float sx[88];
    __shared__ int   scol[CAPR];
    __shared__ float sval[CAPR];

    if (tid < 32) {
        float v = (tid < TT) ? histr[tid] : -1e30f;
#pragma unroll
        for (int off = 16; off > 0; off >>= 1)
            v = fmaxf(v, __shfl_xor_sync(0xffffffffu, v, off));
        if (tid == 0) {
            g_level[r] = v;
            s_inv = (v != 0.0f) ? (1.0f / v) : 0.0f;
        }
    }
    __syncthreads();
    const float inv = s_inv;
    int nodeid = nid[r];

    // pass 1: write x, count mid nonzeros per thread
    int ln = 0;
    for (int c4 = tid; c4 < DP / 4; c4 += 256) {
        int c = c4 * 4;
        float4 v;
        if (c < TT) {
            v.x = histr[c] * inv; v.y = histr[c + 1] * inv;
            v.z = histr[c + 2] * inv; v.w = histr[c + 3] * inv;
        } else if (c < TT + NBN * TT) {
            int u  = c - TT;
            int m  = u / TT;
            int t0 = u - m * TT;
            float a = adjr[m];
            const float* hm = histb + m * TT + t0;
            v.x = fmaxf(fmaf(a * hm[0], inv, -1.0f), 0.0f);
            v.y = fmaxf(fmaf(a * hm[1], inv, -1.0f), 0.0f);
            v.z = fmaxf(fmaf(a * hm[2], inv, -1.0f), 0.0f);
            v.w = fmaxf(fmaf(a * hm[3], inv, -1.0f), 0.0f);
            ln += (v.x > 0.f) + (v.y > 0.f) + (v.z > 0.f) + (v.w > 0.f);
        } else if (c < DD) {
            const float* e = emb + (size_t)nodeid * NIDC + (c - (TT + NBN * TT));
            v.x = e[0]; v.y = e[1]; v.z = e[2]; v.w = e[3];
        } else {
            v.x = v.y = v.z = v.w = 0.0f;
        }
        reinterpret_cast<float4*>(xr + c)[0] = v;
    }
    s_c[tid] = ln;
    __syncthreads();
    // Hillis-Steele inclusive scan over 256 counts (barriers uniform)
    for (int off = 1; off < 256; off <<= 1) {
        int add = (tid >= off) ? s_c[tid - off] : 0;
        __syncthreads();
        s_c[tid] += add;
        __syncthreads();
    }
    int base = s_c[tid] - ln;

    // pass 2: re-read own just-written mid groups (L1-hot), scatter into smem
    int w = 0;
    for (int c4 = tid; c4 < 3078; c4 += 256) {
        if (c4 < 6) continue;                 // head region
        float4 v = reinterpret_cast<const float4*>(xr + c4 * 4)[0];
        float vv[4] = {v.x, v.y, v.z, v.w};
#pragma unroll
        for (int e = 0; e < 4; e++)
            if (vv[e] > 0.0f) {
                int pos = base + w;
                if (pos < CAPR) { scol[pos] = c4 * 4 + e; sval[pos] = vv[e]; }
                w++;
            }
    }
    if (tid < 24)      sx[tid] = xr[tid];
    else if (tid < 88) sx[tid] = xr[12312 + (tid - 24)];
    __syncthreads();

    // fc0: one output column per thread (fp32 input layer for block 0)
    const int cnt = min(s_c[255], CAPR);
    float a = 0.0f;
#pragma unroll 8
    for (int j = 0; j < 88; j++) {
        int c = (j < 24) ? j : 12312 + (j - 24);
        a = fmaf(sx[j], W[(size_t)c * HIDC + tid], a);
    }
    for (int j = 0; j < cnt; j++)
        a = fmaf(sval[j], W[(size_t)scol[j] * HIDC + tid], a);
    out[(size_t)r * HIDC + tid] = tf32r(fmaxf(a + bias[tid], 0.0f));
}

// ---------------- TF32 GEMM, asymmetric deep pipeline ----------------
// EPI 0: Out = tf32r(relu(acc + bias[n]))
// EPI 1: Out = relu(Xin - acc - bias[n])   (+ zero-fill DP pad cols)
// EPI 2: Out[z-slice] = acc                (split-K partial)
// MODE 1: A raw (ldg+cvt+sts, 2 smem slots), B via cp.async 4-stage (padded src)
// MODE 2: B raw (ldg+cvt+sts, col-guarded, 2 smem slots), A via cp.async 4-stage
template <int BM, int EPI, int MODE>
__global__ __launch_bounds__(256) void gemm_k(
    const float* __restrict__ A, int lda,
    const float* __restrict__ B, int ldb,
    int K, int Nreal,
    const float* __restrict__ bias,
    const float* __restrict__ Xin, int ldx,
    float* __restrict__ Out, int ldo)
{
    constexpr int BN = 128, KT = 16;
    constexpr int WM = BM / 2;
    constexpr int MT = WM / 16;
    constexpr int NA = (MODE == 1) ? 2 : 4;
    constexpr int NB = (MODE == 2) ? 2 : 4;
    constexpr int ASTR = BM * 20 * 4;
    constexpr int BSTR = KT * 136 * 4;
    constexpr int ATOT = NA * ASTR;
    constexpr int PIPEB  = ATOT + NB * BSTR;
    constexpr int CBYTES = 64 * 132 * 4;
    constexpr int RAWB   = PIPEB > CBYTES ? PIPEB : CBYTES;

    __shared__ __align__(16) char raw[RAWB];
    const uint32_t sbase = (uint32_t)__cvta_generic_to_shared(raw);

    const int tid  = threadIdx.x;
    const int warp = tid >> 5, lane = tid & 31;
    const int wm = warp >> 2, wn = warp & 3;
    const int gid = lane >> 2, tig = lane & 3;
    const int m0 = blockIdx.y * BM;
    const int n0 = blockIdx.x * BN;
    const int lt = lane >> 3, lr = lane & 7;
    const uint32_t aAddr0 = sbase +
        (uint32_t)(((wm * WM + lr + ((lt & 1) << 3)) * 20 + ((lt >> 1) << 2)) * 4);

    float acc[MT][4][4];
#pragma unroll
    for (int mi = 0; mi < MT; mi++)
#pragma unroll
        for (int ni = 0; ni < 4; ni++)
#pragma unroll
            for (int e = 0; e < 4; e++) acc[mi][ni][e] = 0.0f;

    const int arow = tid >> 2;                // 0..63
    const int akc  = (tid & 3) * 4;
    const int bkr  = tid >> 5;                // 0..7
    const int bcf  = (tid & 31) * 4;

    auto cpA = [&](int kt, int st) {
        cpa16(sbase + st * ASTR + (arow * 20 + akc) * 4,
              A + (size_t)(m0 + arow) * lda + kt * KT + akc);
    };
    auto cpB = [&](int kt, int st) {
#pragma unroll
        for (int i2 = 0; i2 < 2; i2++) {
            int kr = bkr + i2 * 8;
            cpa16(sbase + ATOT + st * BSTR + (kr * 136 + bcf) * 4,
                  B + (size_t)(kt * KT + kr) * ldb + n0 + bcf);
        }
    };
    float4 aR[3];
    auto ldgA = [&](int kt, int sl) {
        aR[sl] = *reinterpret_cast<const float4*>(A + (size_t)(m0 + arow) * lda + kt * KT + akc);
    };
    auto stsA = [&](int st, int sl) {
        float4 v = aR[sl];
        v.x = tf32r(v.x); v.y = tf32r(v.y); v.z = tf32r(v.z); v.w = tf32r(v.w);
        *reinterpret_cast<float4*>(raw + st * ASTR + (arow * 20 + akc) * 4) = v;
    };
    float4 bRg[3][2];
    auto ldgB = [&](int kt, int sl) {
#pragma unroll
        for (int i2 = 0; i2 < 2; i2++) {
            int kr = bkr + i2 * 8;
            int c  = n0 + bcf;
            bRg[sl][i2] = (c + 4 <= Nreal)
                ? *reinterpret_cast<const float4*>(B + (size_t)(kt * KT + kr) * ldb + c)
                : make_float4(0.f, 0.f, 0.f, 0.f);
        }
    };
    auto stsB = [&](int st, int sl) {
#pragma unroll
        for (int i2 = 0; i2 < 2; i2++) {
            int kr = bkr + i2 * 8;
            float4 v = bRg[sl][i2];
            v.x = tf32r(v.x); v.y = tf32r(v.y); v.z = tf32r(v.z); v.w = tf32r(v.w);
            *reinterpret_cast<float4*>(raw + ATOT + st * BSTR + (kr * 136 + bcf) * 4) = v;
        }
    };

    auto compute = [&](int sa, int sb) {
        const uint32_t ap = aAddr0 + (uint32_t)(sa * ASTR);
        const float* Bp = reinterpret_cast<const float*>(raw + ATOT + sb * BSTR);
#pragma unroll
        for (int sub = 0; sub < 2; sub++) {
            int kb = sub * 8;
            unsigned af[MT][4];
#pragma unroll
            for (int mi = 0; mi < MT; mi++)
                ldsm4(af[mi], ap + mi * (16 * 20 * 4) + sub * 32);
            unsigned bfr[4][2];
#pragma unroll
            for (int ni = 0; ni < 4; ni++) {
                int c = wn * 32 + ni * 8 + gid;
                bfr[ni][0] = __float_as_uint(Bp[(kb + tig) * 136 + c]);
                bfr[ni][1] = __float_as_uint(Bp[(kb + tig + 4) * 136 + c]);
            }
#pragma unroll
            for (int mi = 0; mi < MT; mi++)
#pragma unroll
                for (int ni = 0; ni < 4; ni++)
                    mma8(acc[mi][ni], af[mi], bfr[ni]);
        }
    };

    const int nk_total = (K + KT - 1) / KT;
    const int per = (nk_total + gridDim.z - 1) / gridDim.z;
    const int kt0 = blockIdx.z * per;
    const int kt1 = min(nk_total, kt0 + per);
    // all launch configs have kt1-kt0 >= 16, so unguarded depth-3 prologue is safe

    if (MODE == 1) {
        ldgA(kt0, 0); ldgA(kt0 + 1, 1); ldgA(kt0 + 2, 2);
        stsA(0, 0);
        cpB(kt0, 0); cp_commit();
        cpB(kt0 + 1, 1); cp_commit();
        cpB(kt0 + 2, 2); cp_commit();
    } else {
        ldgB(kt0, 0); ldgB(kt0 + 1, 1); ldgB(kt0 + 2, 2);
        stsB(0, 0);
        cpA(kt0, 0); cp_commit();
        cpA(kt0 + 1, 1); cp_commit();
        cpA(kt0 + 2, 2); cp_commit();
    }
    cp_wait2();
    __syncthreads();

    for (int kt = kt0; kt < kt1; kt++) {
        const int i = kt - kt0;
        if (MODE == 1) {
            if (kt + 1 < kt1) stsA((i + 1) & 1, (i + 1) % 3);
            if (kt + 3 < kt1) cpB(kt + 3, (i + 3) & 3);
            cp_commit();
            if (kt + 3 < kt1) ldgA(kt + 3, i % 3);
            compute(i & 1, i & 3);
        } else {
            if (kt + 1 < kt1) stsB((i + 1) & 1, (i + 1) % 3);
            if (kt + 3 < kt1) cpA(kt + 3, (i + 3) & 3);
            cp_commit();
            if (kt + 3 < kt1) ldgB(kt + 3, i % 3);
            compute(i & 3, i & 1);
        }
        cp_wait2();
        __syncthreads();
    }

    // ---------------- staged, fully-coalesced epilogue ----------------
    const size_t zoff = (EPI == 2) ? (size_t)blockIdx.z * MM * HIDC : 0;
    float* Cs = reinterpret_cast<float*>(raw);
#pragma unroll
    for (int half = 0; half < BM / 64; half++) {
        if (((wm * WM) >> 6) == half) {
#pragma unroll
            for (int mi = 0; mi < MT; mi++)
#pragma unroll
                for (int ni = 0; ni < 4; ni++)
#pragma unroll
                    for (int e = 0; e < 4; e++) {
                        int rl = wm * WM + mi * 16 + gid + ((e >> 1) << 3) - half * 64;
                        int cl = wn * 32 + ni * 8 + tig * 2 + (e & 1);
                        Cs[rl * 132 + cl] = acc[mi][ni][e];
                    }
        }
        __syncthreads();
#pragma unroll
        for (int j = 0; j < 8; j++) {
            int idx = tid + j * 256;
            int rl = idx >> 5, c4 = idx & 31;
            int row = m0 + half * 64 + rl;
            int gc  = n0 + c4 * 4;
            if (gc + 4 <= Nreal) {
                float4 a = *reinterpret_cast<const float4*>(&Cs[rl * 132 + c4 * 4]);
                if (EPI == 0) {
                    float4 bv = *reinterpret_cast<const float4*>(bias + gc);
                    float4 r;
                    r.x = tf32r(fmaxf(a.x + bv.x, 0.0f));
                    r.y = tf32r(fmaxf(a.y + bv.y, 0.0f));
                    r.z = tf32r(fmaxf(a.z + bv.z, 0.0f));
                    r.w = tf32r(fmaxf(a.w + bv.w, 0.0f));
                    *reinterpret_cast<float4*>(Out + (size_t)row * ldo + gc) = r;
                } else if (EPI == 1) {
                    float4 xv = *reinterpret_cast<const float4*>(Xin + (size_t)row * ldx + gc);
                    float4 bv = *reinterpret_cast<const float4*>(bias + gc);
                    float4 r;
                    r.x = fmaxf(xv.x - a.x - bv.x, 0.0f);
                    r.y = fmaxf(xv.y - a.y - bv.y, 0.0f);
                    r.z = fmaxf(xv.z - a.z - bv.z, 0.0f);
                    r.w = fmaxf(xv.w - a.w - bv.w, 0.0f);
                    *reinterpret_cast<float4*>(Out + (size_t)row * ldo + gc) = r;
                } else {
                    *reinterpret_cast<float4*>(Out + zoff + (size_t)row * ldo + gc) = a;
                }
            } else if (EPI == 1 && gc + 4 <= ldo) {
                *reinterpret_cast<float4*>(Out + (size_t)row * ldo + gc) =
                    make_float4(0.f, 0.f, 0.f, 0.f);
            }
        }
        __syncthreads();
    }
}

// ---------------- split-K reduce: out = tf32r(relu(sum_s part[s] + bias)) ----------------
__global__ void reduce_relu_kernel(const float* __restrict__ part,
                                   const float* __restrict__ bias,
                                   float* __restrict__ out, int S) {
    int idx = blockIdx.x * blockDim.x + threadIdx.x;
    const float4* p4 = reinterpret_cast<const float4*>(part);
    size_t stride4 = (size_t)MM * HIDC / 4;
    float4 a = p4[idx];
    for (int s = 1; s < S; s++) {
        float4 b = p4[idx + (size_t)s * stride4];
        a.x += b.x; a.y += b.y; a.z += b.z; a.w += b.w;
    }
    int col = (idx * 4) & (HIDC - 1);
    float4 bv = *reinterpret_cast<const float4*>(bias + col);
    float4 r;
    r.x = tf32r(fmaxf(a.x + bv.x, 0.0f));
    r.y = tf32r(fmaxf(a.y + bv.y, 0.0f));
    r.z = tf32r(fmaxf(a.z + bv.z, 0.0f));
    r.w = tf32r(fmaxf(a.w + bv.w, 0.0f));
    reinterpret_cast<float4*>(out)[idx] = r;
}

// ---------------- forecast: F (+)= h @ W_f + b_f ; final: out = F * level ----------------
__global__ void forecast_kernel(const float* __restrict__ h, const float* __restrict__ Wf,
                                const float* __restrict__ bf, int mode,
                                float* __restrict__ outF) {
    __shared__ float sW[HIDC * HORC];
    for (int i = threadIdx.x; i < HIDC * HORC; i += blockDim.x) sW[i] = Wf[i];
    __syncthreads();
    int idx = blockIdx.x * blockDim.x + threadIdx.x;
    int r = idx / HORC, o = idx - r * HORC;
    const float* hr = h + (size_t)r * HIDC;
    float a = 0.0f;
#pragma unroll 8
    for (int k = 0; k < HIDC; k++) a = fmaf(hr[k], sW[k * HORC + o], a);
    a += bf[o];
    if (mode == 0)      g_F[idx] = a;
    else if (mode == 1) g_F[idx] += a;
    else                outF[idx] = (g_F[idx] + a) * g_level[r];
}

// ---------------- launch ----------------
extern "C" void kernel_launch(void* const* d_in, const int* in_sizes, int n_in,
                              void* d_out, int out_size) {
    const float* hist = (const float*)d_in[0];
    const int*   nid  = (const int*)  d_in[1];
    const float* adj  = (const float*)d_in[3];
    const float* emb  = (const float*)d_in[4];
    const float* Win  = (const float*)d_in[5];
    const float* bin  = (const float*)d_in[6];
    const float* Whid = (const float*)d_in[7];
    const float* bhid = (const float*)d_in[8];
    const float* Wf   = (const float*)d_in[9];
    const float* bf   = (const float*)d_in[10];
    const float* Wb   = (const float*)d_in[11];
    const float* bb   = (const float*)d_in[12];
    float* out = (float*)d_out;

    float *px, *pbc, *phA, *phB, *ppart, *pwinr;
    cudaGetSymbolAddress((void**)&px,    g_x);
    cudaGetSymbolAddress((void**)&pbc,   g_bc);
    cudaGetSymbolAddress((void**)&phA,   g_hA);
    cudaGetSymbolAddress((void**)&phB,   g_hB);
    cudaGetSymbolAddress((void**)&ppart, g_part);
    cudaGetSymbolAddress((void**)&pwinr, g_winr);

    constexpr int SA = 8;
    constexpr int RED_GRID = (MM * HIDC / 4) / 256;  // 1024
    constexpr int WIN_GRID = (3 * DP * HIDC / 4 + 255) / 256;

    // launch #1: build x + sparse compaction + block-0 input layer
    bx_fc0_kernel<<<MM, 256>>>(hist, nid, adj, emb, Win, bin, phA);

    float* xin = px;
    float* bcout[3] = { pbc, px, out };

    for (int i = 0; i < 3; i++) {
        if (i > 0) {
            // h = relu(bc @ W_in + b_in): MODE1 (raw A, padded rounded B), split-K
            gemm_k<64, 2, 1><<<dim3(2, 64, SA), 256>>>(
                xin, DP, pwinr + (size_t)i * DP * HIDC, HIDC, DD, HIDC,
                nullptr, nullptr, 0, ppart, HIDC);
            reduce_relu_kernel<<<RED_GRID, 256>>>(ppart, bin + i * HIDC, phA, SA);
        }

        // hidden layers: MODE2 (raw Whid, rounded in regs), fused bias+relu
        gemm_k<64, 0, 2><<<dim3(2, 64), 256>>>(
            phA, HIDC, Whid + (size_t)(i * 2 + 0) * HIDC * HIDC, HIDC,
            HIDC, HIDC, bhid + (i * 2 + 0) * HIDC, nullptr, 0, phB, HIDC);
        gemm_k<64, 0, 2><<<dim3(2, 64), 256>>>(
            phB, HIDC, Whid + (size_t)(i * 2 + 1) * HIDC * HIDC, HIDC,
            HIDC, HIDC, bhid + (i * 2 + 1) * HIDC, nullptr, 0, phA, HIDC);

        // backcast = relu(x - (h @ W_b + b_b)): MODE2 (raw Wb, col-guarded)
        // block 0: this is launch #4 -> ncu capture target
        int ldo = (i == 2) ? DD : DP;
        gemm_k<64, 1, 2><<<dim3(97, 64), 256>>>(
            phA, HIDC, Wb + (size_t)i * HIDC * DD, DD,
            HIDC, DD, bb + (size_t)i * DD, xin, DP, bcout[i], ldo);

        if (i == 0) prep_win_kernel<<<WIN_GRID, 256>>>(Win);  // before block-1 GEMM-A

        // forecast accumulation (reads final h = phA)
        forecast_kernel<<<512, 192>>>(phA, Wf + (size_t)i * HIDC * HORC, bf + i * HORC,
                                      i, out + (size_t)MM * DD);

        xin = bcout[i];
    }
}

// round 17
// speedup vs baseline: 1.0754x; 1.0754x over previous
#include <cuda_runtime.h>
#include <cstdint>

#define DI __device__ __forceinline__

// ---------------- problem constants ----------------
constexpr int NBN  = 512;                 // nodes
constexpr int TT   = 24;                  // T
constexpr int HIDC = 256;
constexpr int HORC = 24;
constexpr int NIDC = 64;
constexpr int DD   = TT + NBN * TT + NIDC; // 12376
constexpr int DP   = 12384;               // padded (= 774*16)
constexpr int MM   = 8 * NBN;             // 4096 rows
constexpr int SPLIT_MAX = 8;
constexpr int CAPR = 4096;                // sparse cap per row (smem)
constexpr int WBN  = 12416;               // padded N for W_b (97*128)

// ---------------- scratch (__device__ globals; no allocs) ----------------
__device__ float g_x   [(size_t)MM * DP];               // ~203 MB
__device__ float g_bc  [(size_t)MM * DP];               // ~203 MB
__device__ float g_part[(size_t)SPLIT_MAX * MM * HIDC]; // 33.5 MB split-K partials
__device__ float g_hA[MM * HIDC];
__device__ float g_hB[MM * HIDC];
__device__ float g_F [MM * HORC];
__device__ float g_level[MM];
// transposed + tf32-rounded + zero-padded weights (n-major for ldmatrix B-frags)
__device__ float g_wbtr [(size_t)3 * WBN * HIDC];       // Wb^T  [n=12416][k=256]
__device__ float g_wintr[(size_t)3 * HIDC * DP];        // Win^T [n=256][k=12384]
__device__ float g_whtr [(size_t)6 * HIDC * HIDC];      // Whid^T [n=256][k=256]

// ---------------- helpers ----------------
DI float tf32r(float x) {                 // round-to-nearest TF32 (fp32 container)
    unsigned o;
    asm("cvt.rna.tf32.f32 %0, %1;" : "=r"(o) : "f"(x));
    return __uint_as_float(o);
}

DI void mma8(float c[4], const unsigned a[4], unsigned b0, unsigned b1) {
    asm volatile(
        "mma.sync.aligned.m16n8k8.row.col.f32.tf32.tf32.f32 "
        "{%0,%1,%2,%3}, {%4,%5,%6,%7}, {%8,%9}, {%0,%1,%2,%3};\n"
        : "+f"(c[0]), "+f"(c[1]), "+f"(c[2]), "+f"(c[3])
        : "r"(a[0]), "r"(a[1]), "r"(a[2]), "r"(a[3]),
          "r"(b0), "r"(b1));
}

DI void ldsm4(unsigned r[4], uint32_t addr) {
    asm volatile("ldmatrix.sync.aligned.m8n8.x4.shared.b16 {%0,%1,%2,%3}, [%4];"
                 : "=r"(r[0]), "=r"(r[1]), "=r"(r[2]), "=r"(r[3]) : "r"(addr));
}

DI void cpa16(uint32_t saddr, const float* g) {
    asm volatile("cp.async.ca.shared.global [%0], [%1], 16;" :: "r"(saddr), "l"(g));
}
DI void cp_commit() { asm volatile("cp.async.commit_group;"); }
DI void cp_wait1()  { asm volatile("cp.async.wait_group 1;"); }

// ---------------- transpose + round + pad: dst[n][k] = tf32r(src[k][n]) ----------------
// src: [Kr][Nr] row-major; dst: [Nd][Kd] row-major, zero-filled outside real dims.
// Kd, Nd multiples of 32.
__global__ __launch_bounds__(256) void transpose_round_kernel(
        const float* __restrict__ src, float* __restrict__ dst,
        int Kr, int Nr, int Kd, int Nd, long sStride, long dStride) {
    __shared__ float t[32][33];
    src += (size_t)blockIdx.z * sStride;
    dst += (size_t)blockIdx.z * dStride;
    int k0 = blockIdx.x * 32, n0 = blockIdx.y * 32;
    int tx = threadIdx.x, ty = threadIdx.y;
#pragma unroll
    for (int j = 0; j < 4; j++) {
        int k = k0 + ty + j * 8, n = n0 + tx;
        t[ty + j * 8][tx] = (k < Kr && n < Nr) ? src[(size_t)k * Nr + n] : 0.0f;
    }
    __syncthreads();
#pragma unroll
    for (int j = 0; j < 4; j++)
        dst[(size_t)(n0 + ty + j * 8) * Kd + k0 + tx] = tf32r(t[tx][ty + j * 8]);
}

// ---------------- fused: build x + sparse compaction + block-0 input layer ----------------
__global__ __launch_bounds__(256) void bx_fc0_kernel(
        const float* __restrict__ hist, const int* __restrict__ nid,
        const float* __restrict__ adj,  const float* __restrict__ emb,
        const float* __restrict__ W,    const float* __restrict__ bias,
        float* __restrict__ out) {
    int r = blockIdx.x;
    const int tid = threadIdx.x;
    const float* adjr  = adj  + (size_t)r * NBN;
    const float* histb = hist + (size_t)(r >> 9) * NBN * TT;
    const float* histr = hist + (size_t)r * TT;
    float* xr = g_x + (size_t)r * DP;

    __shared__ float s_inv;
    __shared__ int   s_c[256];
    __shared__ float sx[88];
    __shared__ int   scol[CAPR];
    __shared__ float sval[CAPR];

    if (tid < 32) {
        float v = (tid < TT) ? histr[tid] : -1e30f;
#pragma unroll
        for (int off = 16; off > 0; off >>= 1)
            v = fmaxf(v, __shfl_xor_sync(0xffffffffu, v, off));
        if (tid == 0) {
            g_level[r] = v;
            s_inv = (v != 0.0f) ? (1.0f / v) : 0.0f;
        }
    }
    __syncthreads();
    const float inv = s_inv;
    int nodeid = nid[r];

    // pass 1: write x, count mid nonzeros per thread
    int ln = 0;
    for (int c4 = tid; c4 < DP / 4; c4 += 256) {
        int c = c4 * 4;
        float4 v;
        if (c < TT) {
            v.x = histr[c] * inv; v.y = histr[c + 1] * inv;
            v.z = histr[c + 2] * inv; v.w = histr[c + 3] * inv;
        } else if (c < TT + NBN * TT) {
            int u  = c - TT;
            int m  = u / TT;
            int t0 = u - m * TT;
            float a = adjr[m];
            const float* hm = histb + m * TT + t0;
            v.x = fmaxf(fmaf(a * hm[0], inv, -1.0f), 0.0f);
            v.y = fmaxf(fmaf(a * hm[1], inv, -1.0f), 0.0f);
            v.z = fmaxf(fmaf(a * hm[2], inv, -1.0f), 0.0f);
            v.w = fmaxf(fmaf(a * hm[3], inv, -1.0f), 0.0f);
            ln += (v.x > 0.f) + (v.y > 0.f) + (v.z > 0.f) + (v.w > 0.f);
        } else if (c < DD) {
            const float* e = emb + (size_t)nodeid * NIDC + (c - (TT + NBN * TT));
            v.x = e[0]; v.y = e[1]; v.z = e[2]; v.w = e[3];
        } else {
            v.x = v.y = v.z = v.w = 0.0f;
        }
        reinterpret_cast<float4*>(xr + c)[0] = v;
    }
    s_c[tid] = ln;
    __syncthreads();
    for (int off = 1; off < 256; off <<= 1) {   // uniform-barrier scan
        int add = (tid >= off) ? s_c[tid - off] : 0;
        __syncthreads();
        s_c[tid] += add;
        __syncthreads();
    }
    int base = s_c[tid] - ln;

    // pass 2: re-read own mid groups (L1-hot), scatter nonzeros into smem
    int w = 0;
    for (int c4 = tid; c4 < 3078; c4 += 256) {
        if (c4 < 6) continue;
        float4 v = reinterpret_cast<const float4*>(xr + c4 * 4)[0];
        float vv[4] = {v.x, v.y, v.z, v.w};
#pragma unroll
        for (int e = 0; e < 4; e++)
            if (vv[e] > 0.0f) {
                int pos = base + w;
                if (pos < CAPR) { scol[pos] = c4 * 4 + e; sval[pos] = vv[e]; }
                w++;
            }
    }
    if (tid < 24)      sx[tid] = xr[tid];
    else if (tid < 88) sx[tid] = xr[12312 + (tid - 24)];
    __syncthreads();

    // fc0: one output column per thread
    const int cnt = min(s_c[255], CAPR);
    float a = 0.0f;
#pragma unroll 8
    for (int j = 0; j < 88; j++) {
        int c = (j < 24) ? j : 12312 + (j - 24);
        a = fmaf(sx[j], W[(size_t)c * HIDC + tid], a);
    }
    for (int j = 0; j < cnt; j++)
        a = fmaf(sval[j], W[(size_t)scol[j] * HIDC + tid], a);
    out[(size_t)r * HIDC + tid] = tf32r(fmaxf(a + bias[tid], 0.0f));
}

// ---------------- TF32 GEMM: 128 threads, warps 2x2, warp tile 32 x (BN/2) ----------------
// B operand is TRANSPOSED (n-major) in gmem & smem -> ldmatrix.x4 B fragments.
// EPI 0: Out = tf32r(relu(acc + bias[n]))
// EPI 1: Out = relu(Xin - acc - bias[n])   (+ zero-fill DP pad cols)
// EPI 2: Out[z-slice] = acc                (split-K partial)
// MODE 0: A via cp.async (source already tf32-rounded), 3-stage
// MODE 1: A raw (ldg + cvt + sts, 2 slots, distance-3 regs), B cp.async 3-stage
template <int BN, int EPI, int MODE>
__global__ __launch_bounds__(128) void gemm_k(
    const float* __restrict__ A, int lda,
    const float* __restrict__ Bt, int ldbT,      // [N][K] n-major, padded
    int K, int Nreal,
    const float* __restrict__ bias,
    const float* __restrict__ Xin, int ldx,
    float* __restrict__ Out, int ldo)
{
    constexpr int BM = 64, KT = 16;
    constexpr int WN = BN / 2;                   // warp n-size
    constexpr int NI = WN / 8;                   // 8 (BN=128) or 4 (BN=64)
    constexpr int NA   = (MODE == 1) ? 2 : 3;
    constexpr int BROWP = 20;                    // smem row pitch (floats), 16B-aligned rows
    constexpr int ASTR = BM * BROWP * 4;         // 5120
    constexpr int BSTR = BN * BROWP * 4;         // 10240 / 5120
    constexpr int ATOT = NA * ASTR;
    constexpr int CP   = BN + 4;
    constexpr int CBYTES = BM * CP * 4;
    constexpr int PIPEB  = ATOT + 3 * BSTR;
    constexpr int RAWB   = PIPEB > CBYTES ? PIPEB : CBYTES;

    __shared__ __align__(16) char raw[RAWB];
    const uint32_t sbase = (uint32_t)__cvta_generic_to_shared(raw);

    const int tid  = threadIdx.x;
    const int warp = tid >> 5, lane = tid & 31;
    const int wm = warp >> 1, wn = warp & 1;
    const int gid = lane >> 2, tig = lane & 3;
    const int m0 = blockIdx.y * BM;
    const int n0 = blockIdx.x * BN;

    // A ldmatrix base (proven mapping): tiles (rows+0/8) x (kwords 0-3/4-7)
    const int lt = lane >> 3, lr = lane & 7;
    const uint32_t aAddr0 = sbase +
        (uint32_t)(((wm * 32 + lr + ((lt & 1) << 3)) * BROWP + ((lt >> 1) << 2)) * 4);
    // B ldmatrix base: lane l -> row (((l>>4)&1)*8 + (l&7)), kword ((l>>3)&1)*4
    const int bRow  = ((lane >> 4) << 3) + (lane & 7);
    const int bWord = ((lane >> 3) & 1) << 2;
    const uint32_t bAddr0 = sbase + (uint32_t)ATOT +
        (uint32_t)(((wn * WN + bRow) * BROWP + bWord) * 4);

    float acc[2][NI][4];
#pragma unroll
    for (int mi = 0; mi < 2; mi++)
#pragma unroll
        for (int ni = 0; ni < NI; ni++)
#pragma unroll
            for (int e = 0; e < 4; e++) acc[mi][ni][e] = 0.0f;

    // cp.async chunk maps: A 256 chunks (r=c>>2, w=(c&3)*4); B BN*4 chunks
    auto cpA = [&](int kt, int st) {
#pragma unroll
        for (int u = 0; u < 2; u++) {
            int c = tid + u * 128, r = c >> 2, w = (c & 3) * 4;
            cpa16(sbase + st * ASTR + (r * BROWP + w) * 4,
                  A + (size_t)(m0 + r) * lda + kt * KT + w);
        }
    };
    auto cpB = [&](int kt, int st) {
#pragma unroll
        for (int u = 0; u < BN / 32; u++) {
            int c = tid + u * 128, r = c >> 2, w = (c & 3) * 4;
            cpa16(sbase + ATOT + st * BSTR + (r * BROWP + w) * 4,
                  Bt + (size_t)(n0 + r) * ldbT + kt * KT + w);
        }
    };
    float4 aR[3][2];
    auto ldgA = [&](int kt, int sl) {
#pragma unroll
        for (int u = 0; u < 2; u++) {
            int c = tid + u * 128, r = c >> 2, w = (c & 3) * 4;
            aR[sl][u] = *reinterpret_cast<const float4*>(
                A + (size_t)(m0 + r) * lda + kt * KT + w);
        }
    };
    auto stsA = [&](int st, int sl) {
#pragma unroll
        for (int u = 0; u < 2; u++) {
            int c = tid + u * 128, r = c >> 2, w = (c & 3) * 4;
            float4 v = aR[sl][u];
            v.x = tf32r(v.x); v.y = tf32r(v.y); v.z = tf32r(v.z); v.w = tf32r(v.w);
            *reinterpret_cast<float4*>(raw + st * ASTR + (r * BROWP + w) * 4) = v;
        }
    };

    auto compute = [&](int sa, int sb) {
        const uint32_t ap = aAddr0 + (uint32_t)(sa * ASTR);
        const uint32_t bp = bAddr0 + (uint32_t)(sb * BSTR);
#pragma unroll
        for (int sub = 0; sub < 2; sub++) {
            unsigned af[2][4];
            ldsm4(af[0], ap + sub * 32);
            ldsm4(af[1], ap + 16 * BROWP * 4 + sub * 32);
#pragma unroll
            for (int p = 0; p < NI / 2; p++) {
                unsigned bq[4];
                ldsm4(bq, bp + p * (16 * BROWP * 4) + sub * 32);
#pragma unroll
                for (int mi = 0; mi < 2; mi++) {
                    mma8(acc[mi][2 * p],     af[mi], bq[0], bq[1]);
                    mma8(acc[mi][2 * p + 1], af[mi], bq[2], bq[3]);
                }
            }
        }
    };

    const int nk_total = (K + KT - 1) / KT;
    const int per = (nk_total + gridDim.z - 1) / gridDim.z;
    const int kt0 = blockIdx.z * per;
    const int kt1 = min(nk_total, kt0 + per);
    // every launch config has kt1-kt0 >= 16: unguarded depth-2/3 prologue OK

    if (MODE == 1) {
        ldgA(kt0, 0); ldgA(kt0 + 1, 1); ldgA(kt0 + 2, 2);
        stsA(0, 0);
        cpB(kt0, 0);     cp_commit();
        cpB(kt0 + 1, 1); cp_commit();
    } else {
        cpA(kt0, 0);     cpB(kt0, 0);     cp_commit();
        cpA(kt0 + 1, 1); cpB(kt0 + 1, 1); cp_commit();
    }
    cp_wait1();
    __syncthreads();

    for (int kt = kt0; kt < kt1; kt++) {
        const int i = kt - kt0;
        if (MODE == 1) {
            if (kt + 1 < kt1) stsA((i + 1) & 1, (i + 1) % 3);
            if (kt + 2 < kt1) cpB(kt + 2, (i + 2) % 3);
            cp_commit();
            if (kt + 3 < kt1) ldgA(kt + 3, i % 3);
            compute(i & 1, i % 3);
        } else {
            if (kt + 2 < kt1) { cpA(kt + 2, (i + 2) % 3); cpB(kt + 2, (i + 2) % 3); }
            cp_commit();
            compute(i % 3, i % 3);
        }
        cp_wait1();
        __syncthreads();
    }

    // ---------------- staged, fully-coalesced epilogue ----------------
    const size_t zoff = (EPI == 2) ? (size_t)blockIdx.z * MM * HIDC : 0;
    float* Cs = reinterpret_cast<float*>(raw);
#pragma unroll
    for (int mi = 0; mi < 2; mi++)
#pragma unroll
        for (int ni = 0; ni < NI; ni++)
#pragma unroll
            for (int e = 0; e < 4; e++) {
                int rl = wm * 32 + mi * 16 + gid + ((e >> 1) << 3);
                int cl = wn * WN + ni * 8 + tig * 2 + (e & 1);
                Cs[rl * CP + cl] = acc[mi][ni][e];
            }
    __syncthreads();
    constexpr int F4 = BN / 4;
#pragma unroll
    for (int j = 0; j < (64 * F4) / 128; j++) {
        int idx = tid + j * 128;
        int rl = idx / F4, c4 = idx % F4;
        int row = m0 + rl;
        int gc  = n0 + c4 * 4;
        if (gc + 4 <= Nreal) {
            float4 a = *reinterpret_cast<const float4*>(&Cs[rl * CP + c4 * 4]);
            if (EPI == 0) {
                float4 bv = *reinterpret_cast<const float4*>(bias + gc);
                float4 r;
                r.x = tf32r(fmaxf(a.x + bv.x, 0.0f));
                r.y = tf32r(fmaxf(a.y + bv.y, 0.0f));
                r.z = tf32r(fmaxf(a.z + bv.z, 0.0f));
                r.w = tf32r(fmaxf(a.w + bv.w, 0.0f));
                *reinterpret_cast<float4*>(Out + (size_t)row * ldo + gc) = r;
            } else if (EPI == 1) {
                float4 xv = *reinterpret_cast<const float4*>(Xin + (size_t)row * ldx + gc);
                float4 bv = *reinterpret_cast<const float4*>(bias + gc);
                float4 r;
                r.x = fmaxf(xv.x - a.x - bv.x, 0.0f);
                r.y = fmaxf(xv.y - a.y - bv.y, 0.0f);
                r.z = fmaxf(xv.z - a.z - bv.z, 0.0f);
                r.w = fmaxf(xv.w - a.w - bv.w, 0.0f);
                *reinterpret_cast<float4*>(Out + (size_t)row * ldo + gc) = r;
            } else {
                *reinterpret_cast<float4*>(Out + zoff + (size_t)row * ldo + gc) = a;
            }
        } else if (EPI == 1 && gc + 4 <= ldo) {
            // zero-fill DP pad cols so guard-free downstream A loads see zeros
            *reinterpret_cast<float4*>(Out + (size_t)row * ldo + gc) =
                make_float4(0.f, 0.f, 0.f, 0.f);
        }
    }
}

// ---------------- split-K reduce: out = tf32r(relu(sum_s part[s] + bias)) ----------------
__global__ void reduce_relu_kernel(const float* __restrict__ part,
                                   const float* __restrict__ bias,
                                   float* __restrict__ out, int S) {
    int idx = blockIdx.x * blockDim.x + threadIdx.x;
    const float4* p4 = reinterpret_cast<const float4*>(part);
    size_t stride4 = (size_t)MM * HIDC / 4;
    float4 a = p4[idx];
    for (int s = 1; s < S; s++) {
        float4 b = p4[idx + (size_t)s * stride4];
        a.x += b.x; a.y += b.y; a.z += b.z; a.w += b.w;
    }
    int col = (idx * 4) & (HIDC - 1);
    float4 bv = *reinterpret_cast<const float4*>(bias + col);
    float4 r;
    r.x = tf32r(fmaxf(a.x + bv.x, 0.0f));
    r.y = tf32r(fmaxf(a.y + bv.y, 0.0f));
    r.z = tf32r(fmaxf(a.z + bv.z, 0.0f));
    r.w = tf32r(fmaxf(a.w + bv.w, 0.0f));
    reinterpret_cast<float4*>(out)[idx] = r;
}

// ---------------- forecast: F (+)= h @ W_f + b_f ; final: out = F * level ----------------
__global__ void forecast_kernel(const float* __restrict__ h, const float* __restrict__ Wf,
                                const float* __restrict__ bf, int mode,
                                float* __restrict__ outF) {
    __shared__ float sW[HIDC * HORC];
    for (int i = threadIdx.x; i < HIDC * HORC; i += blockDim.x) sW[i] = Wf[i];
    __syncthreads();
    int idx = blockIdx.x * blockDim.x + threadIdx.x;
    int r = idx / HORC, o = idx - r * HORC;
    const float* hr = h + (size_t)r * HIDC;
    float a = 0.0f;
#pragma unroll 8
    for (int k = 0; k < HIDC; k++) a = fmaf(hr[k], sW[k * HORC + o], a);
    a += bf[o];
    if (mode == 0)      g_F[idx] = a;
    else if (mode == 1) g_F[idx] += a;
    else                outF[idx] = (g_F[idx] + a) * g_level[r];
}

// ---------------- launch ----------------
extern "C" void kernel_launch(void* const* d_in, const int* in_sizes, int n_in,
                              void* d_out, int out_size) {
    const float* hist = (const float*)d_in[0];
    const int*   nid  = (const int*)  d_in[1];
    const float* adj  = (const float*)d_in[3];
    const float* emb  = (const float*)d_in[4];
    const float* Win  = (const float*)d_in[5];
    const float* bin  = (const float*)d_in[6];
    const float* Whid = (const float*)d_in[7];
    const float* bhid = (const float*)d_in[8];
    const float* Wf   = (const float*)d_in[9];
    const float* bf   = (const float*)d_in[10];
    const float* Wb   = (const float*)d_in[11];
    const float* bb   = (const float*)d_in[12];
    float* out = (float*)d_out;

    float *px, *pbc, *phA, *phB, *ppart, *pwbtr, *pwintr, *pwhtr;
    cudaGetSymbolAddress((void**)&px,     g_x);
    cudaGetSymbolAddress((void**)&pbc,    g_bc);
    cudaGetSymbolAddress((void**)&phA,    g_hA);
    cudaGetSymbolAddress((void**)&phB,    g_hB);
    cudaGetSymbolAddress((void**)&ppart,  g_part);
    cudaGetSymbolAddress((void**)&pwbtr,  g_wbtr);
    cudaGetSymbolAddress((void**)&pwintr, g_wintr);
    cudaGetSymbolAddress((void**)&pwhtr,  g_whtr);

    constexpr int SA = 8;
    constexpr int RED_GRID = (MM * HIDC / 4) / 256;  // 1024

    // weight transposes needed before block-0 hidden/backcast
    transpose_round_kernel<<<dim3(8, 8, 6), dim3(32, 8)>>>(
        Whid, pwhtr, HIDC, HIDC, HIDC, HIDC, (long)HIDC * HIDC, (long)HIDC * HIDC);
    transpose_round_kernel<<<dim3(8, WBN / 32, 3), dim3(32, 8)>>>(
        Wb, pwbtr, HIDC, DD, HIDC, WBN, (long)HIDC * DD, (long)WBN * HIDC);

    // build x + sparse compaction + block-0 input layer
    bx_fc0_kernel<<<MM, 256>>>(hist, nid, adj, emb, Win, bin, phA);

    float* xin = px;
    float* bcout[3] = { pbc, px, out };

    for (int i = 0; i < 3; i++) {
        if (i > 0) {
            // h = relu(bc @ W_in + b_in): MODE1 (raw A, transposed padded Win), split-K
            gemm_k<128, 2, 1><<<dim3(2, 64, SA), 128>>>(
                xin, DP, pwintr + (size_t)i * HIDC * DP, DP, DD, HIDC,
                nullptr, nullptr, 0, ppart, HIDC);
            reduce_relu_kernel<<<RED_GRID, 256>>>(ppart, bin + i * HIDC, phA, SA);
        }

        // hidden layers: BN=64 (grid 4x64 -> 1024 warps), both operands cp.async
        gemm_k<64, 0, 0><<<dim3(4, 64), 128>>>(
            phA, HIDC, pwhtr + (size_t)(i * 2 + 0) * HIDC * HIDC, HIDC,
            HIDC, HIDC, bhid + (i * 2 + 0) * HIDC, nullptr, 0, phB, HIDC);
        gemm_k<64, 0, 0><<<dim3(4, 64), 128>>>(
            phB, HIDC, pwhtr + (size_t)(i * 2 + 1) * HIDC * HIDC, HIDC,
            HIDC, HIDC, bhid + (i * 2 + 1) * HIDC, nullptr, 0, phA, HIDC);

        // backcast = relu(x - (h @ W_b + b_b)): transposed padded Wb, guard-free cp.async
        int ldo = (i == 2) ? DD : DP;
        gemm_k<128, 1, 0><<<dim3(WBN / 128, 64), 128>>>(
            phA, HIDC, pwbtr + (size_t)i * WBN * HIDC, HIDC,
            HIDC, DD, bb + (size_t)i * DD, xin, DP, bcout[i], ldo);

        // Win transpose needed only before block-1 GEMM-A
        if (i == 0)
            transpose_round_kernel<<<dim3(DP / 32, 8, 3), dim3(32, 8)>>>(
                Win, pwintr, DD, HIDC, DP, HIDC, (long)DD * HIDC, (long)HIDC * DP);

        // forecast accumulation (reads final h = phA)
        forecast_kernel<<<512, 192>>>(phA, Wf + (size_t)i * HIDC * HORC, bf + i * HORC,
                                      i, out + (size_t)MM * DD);

        xin = bcout[i];
    }
}